// round 2
// baseline (speedup 1.0000x reference)
#include <cuda_runtime.h>
#include <cstdint>

// ---------------- problem constants ----------------
#define NB    4
#define CIN1  512
#define COUT  256
#define HOUT  128          // spatial after upsample
#define NPIX  (HOUT*HOUT)  // 16384

// ---------------- scratch (device globals; no allocation allowed) ----------
__device__ float g_xumod[NB*CIN1*NPIX];      // upsampled & style-modulated input (134 MB)
__device__ float g_h1s2 [NB*COUT*NPIX];      // conv1 output, lrelu'd, pre-scaled by s2 (67 MB)
__device__ float g_w1p  [CIN1*(COUT/64)*576];
__device__ float g_w2p  [COUT*(COUT/64)*576];
__device__ float g_s1[NB*CIN1];
__device__ float g_s2[NB*COUT];
__device__ float g_s3[NB*COUT];
__device__ float g_d1[NB*COUT];
__device__ float g_d2[NB*COUT];
__device__ float g_w3m[NB*3*COUT];

// ---------------- style affine: s = w @ aW^T + aB ----------------
__global__ void style_kernel(const float* __restrict__ w,
                             const float* __restrict__ a1w, const float* __restrict__ a1b,
                             const float* __restrict__ a2w, const float* __restrict__ a2b,
                             const float* __restrict__ a3w, const float* __restrict__ a3b)
{
    int idx = blockIdx.x * blockDim.x + threadIdx.x;   // 0..4095
    const float* arow; const float* bias; float* out; int b, i;
    if (idx < 2048)      { b = idx >> 9;  i = idx & 511; arow = a1w + (size_t)i*512; bias = a1b; out = g_s1 + b*CIN1 + i; }
    else if (idx < 3072) { int t = idx - 2048; b = t >> 8; i = t & 255; arow = a2w + (size_t)i*512; bias = a2b; out = g_s2 + b*COUT + i; }
    else if (idx < 4096) { int t = idx - 3072; b = t >> 8; i = t & 255; arow = a3w + (size_t)i*512; bias = a3b; out = g_s3 + b*COUT + i; }
    else return;
    const float* wrow = w + (size_t)b*512;
    float acc = 0.f;
    #pragma unroll 8
    for (int k = 0; k < 512; ++k) acc = fmaf(wrow[k], arow[k], acc);
    *out = acc + bias[i];
}

// ---------------- demod factors: d[b,o] = rsqrt( sum_i s^2 * sum_k w^2 + eps )
__global__ void demod_kernel(const float* __restrict__ wgt, int CIN, int which)
{
    const float* s = which ? g_s2 : g_s1;
    float*       d = which ? g_d2 : g_d1;
    int o = blockIdx.x;               // 0..255
    int tid = threadIdx.x;            // 256 threads
    float pb[NB] = {0.f, 0.f, 0.f, 0.f};
    for (int i = tid; i < CIN; i += 256) {
        const float* wp = wgt + (size_t)(o*CIN + i)*9;
        float r = 0.f;
        #pragma unroll
        for (int t = 0; t < 9; ++t) { float v = wp[t]; r = fmaf(v, v, r); }
        #pragma unroll
        for (int b = 0; b < NB; ++b) { float sv = s[b*CIN + i]; pb[b] = fmaf(r, sv*sv, pb[b]); }
    }
    __shared__ float red[256];
    for (int b = 0; b < NB; ++b) {
        red[tid] = pb[b];
        __syncthreads();
        for (int st = 128; st > 0; st >>= 1) {
            if (tid < st) red[tid] += red[tid + st];
            __syncthreads();
        }
        if (tid == 0) d[b*COUT + o] = rsqrtf(red[0] + 1e-8f);
        __syncthreads();
    }
}

// ---------------- fold s3 into w3: w3m[b,c,o] = w3[c,o] * s3[b,o] ----------
__global__ void w3m_kernel(const float* __restrict__ w3)
{
    int idx = blockIdx.x * blockDim.x + threadIdx.x;
    if (idx >= NB*3*COUT) return;
    int o = idx & 255;
    int c = (idx >> 8) % 3;
    int b = idx / 768;
    g_w3m[idx] = w3[c*COUT + o] * g_s3[b*COUT + o];
}

// ---------------- weight repack: [o][ci][9] -> [ci][ocb][oi*9+tap] ---------
__global__ void repack_kernel(const float* __restrict__ w, float* __restrict__ wp,
                              int CIN, int OC)
{
    int idx = blockIdx.x * blockDim.x + threadIdx.x;
    if (idx >= OC*CIN*9) return;
    int tap = idx % 9;
    int t   = idx / 9;
    int ci  = t % CIN;
    int o   = t / CIN;
    int ocb = o >> 6, oi = o & 63;
    wp[(size_t)(ci*(OC >> 6) + ocb)*576 + oi*9 + tap] = w[idx];
}

// ---------------- bilinear x2 upsample (half-pixel) + s1 modulation --------
__global__ void upsample_kernel(const float* __restrict__ x)
{
    int idx = blockIdx.x * blockDim.x + threadIdx.x;    // 2^25 total
    int X  = idx & 127;
    int Y  = (idx >> 7) & 127;
    int ci = (idx >> 14) & 511;
    int b  = idx >> 23;
    int jy = Y >> 1, jx = X >> 1;
    int ya = jy + ((Y & 1) ? 0 : -1);
    float wya = (Y & 1) ? 0.75f : 0.25f;
    int yb = ya + 1; float wyb = 1.f - wya;
    int xa = jx + ((X & 1) ? 0 : -1);
    float wxa = (X & 1) ? 0.75f : 0.25f;
    int xb = xa + 1; float wxb = 1.f - wxa;
    ya = max(ya, 0); yb = min(yb, 63);
    xa = max(xa, 0); xb = min(xb, 63);
    const float* src = x + ((size_t)(b*CIN1 + ci) << 12);   // 64*64
    float v = wya * (wxa*src[ya*64 + xa] + wxb*src[ya*64 + xb])
            + wyb * (wxa*src[yb*64 + xa] + wxb*src[yb*64 + xb]);
    g_xumod[idx] = v * g_s1[b*CIN1 + ci];
}

// ---------------- main 3x3 conv (shared weights, per-(b,o) demod epilogue) -
// block: (tile 16x16 px, 64 oc, batch). 256 thr, 8oc x 8px micro-tile/thread.
template<int CIN, bool POST>
__global__ __launch_bounds__(256, 2)
void conv3x3_kernel(const float* __restrict__ in,    // [B,CIN,128,128]
                    const float* __restrict__ wp,    // repacked [ci][ocb][576]
                    const float* __restrict__ bias,  // [OC]
                    const float* __restrict__ demod, // [B,OC]
                    const float* __restrict__ post,  // [B,OC] or unused
                    float* __restrict__ out,         // [B,OC,128,128]
                    int OC)
{
    __shared__ __align__(16) float sIn[2][18*19];
    __shared__ __align__(16) float sW [2][576];

    const int tid    = threadIdx.x;
    const int tileId = blockIdx.x;            // 0..63
    const int ocb    = blockIdx.y;
    const int b      = blockIdx.z;
    const int baseY  = (tileId >> 3) << 4;
    const int baseX  = (tileId & 7) << 4;
    const int ocBase = ocb << 6;
    const int nOcb   = OC >> 6;

    const int lane = tid & 31;
    const int warp = tid >> 5;                // oc group (8 ocs)
    const int row  = lane >> 1;               // 0..15
    const int x0   = (lane & 1) << 3;         // 0 or 8

    float acc[8][8];
    #pragma unroll
    for (int i = 0; i < 8; ++i)
        #pragma unroll
        for (int j = 0; j < 8; ++j) acc[i][j] = 0.f;

    auto loadStage = [&](int ci, int p) {
        const float* inBase = in + ((size_t)(b*CIN + ci) << 14);
        #pragma unroll
        for (int t = tid; t < 324; t += 256) {
            int r = t / 18, c = t % 18;
            int gy = baseY + r - 1, gx = baseX + c - 1;
            uint32_t sa = (uint32_t)__cvta_generic_to_shared(&sIn[p][r*19 + c]);
            if ((unsigned)gy < 128u && (unsigned)gx < 128u) {
                asm volatile("cp.async.ca.shared.global [%0], [%1], 4;\n"
                             :: "r"(sa), "l"(inBase + (gy << 7) + gx));
            } else {
                sIn[p][r*19 + c] = 0.f;
            }
        }
        if (tid < 144) {
            const float* g = wp + (size_t)(ci*nOcb + ocb)*576 + tid*4;
            uint32_t sa = (uint32_t)__cvta_generic_to_shared(&sW[p][tid*4]);
            asm volatile("cp.async.cg.shared.global [%0], [%1], 16;\n"
                         :: "r"(sa), "l"(g));
        }
        asm volatile("cp.async.commit_group;\n");
    };

    loadStage(0, 0);

    for (int ci = 0; ci < CIN; ++ci) {
        int p = ci & 1;
        asm volatile("cp.async.wait_group 0;\n" ::: "memory");
        __syncthreads();
        if (ci + 1 < CIN) loadStage(ci + 1, p ^ 1);

        #pragma unroll
        for (int kh = 0; kh < 3; ++kh) {
            #pragma unroll
            for (int kw = 0; kw < 3; ++kw) {
                float wv[8];
                #pragma unroll
                for (int i = 0; i < 8; ++i)
                    wv[i] = sW[p][(warp*8 + i)*9 + kh*3 + kw];
                #pragma unroll
                for (int j = 0; j < 8; ++j) {
                    float xv = sIn[p][(row + kh)*19 + x0 + kw + j];
                    #pragma unroll
                    for (int i = 0; i < 8; ++i)
                        acc[i][j] = fmaf(wv[i], xv, acc[i][j]);
                }
            }
        }
    }

    // epilogue: demod, bias, leaky-relu, optional post-scale (s2 for conv1)
    #pragma unroll
    for (int i = 0; i < 8; ++i) {
        int o = ocBase + warp*8 + i;
        float d  = demod[b*OC + o];
        float bs = bias[o];
        float ps = POST ? post[b*OC + o] : 1.f;
        float* op = out + ((size_t)(b*OC + o) << 14) + ((baseY + row) << 7) + baseX + x0;
        float v[8];
        #pragma unroll
        for (int j = 0; j < 8; ++j) {
            float t = fmaf(acc[i][j], d, bs);
            t = t > 0.f ? t : 0.2f*t;
            v[j] = POST ? t*ps : t;
        }
        *(float4*)(op)     = make_float4(v[0], v[1], v[2], v[3]);
        *(float4*)(op + 4) = make_float4(v[4], v[5], v[6], v[7]);
    }
}

// ---------------- to_rgb: 1x1 conv over 256 ch, no demod, + bias, lrelu ----
__global__ void rgb_kernel(const float* __restrict__ h,   // [B,256,128,128]
                           const float* __restrict__ b3,
                           float* __restrict__ rgb)       // [B,3,128,128]
{
    int idx = blockIdx.x * blockDim.x + threadIdx.x;      // 0..65535
    int pix = idx & (NPIX - 1);
    int b   = idx >> 14;
    const float* hp = h + ((size_t)b * COUT << 14) + pix;
    const float* wm = g_w3m + b*3*COUT;
    float a0 = 0.f, a1 = 0.f, a2 = 0.f;
    #pragma unroll 4
    for (int o = 0; o < COUT; ++o) {
        float hv = hp[(size_t)o << 14];
        a0 = fmaf(hv, wm[o],            a0);
        a1 = fmaf(hv, wm[COUT + o],     a1);
        a2 = fmaf(hv, wm[2*COUT + o],   a2);
    }
    a0 += b3[0]; a1 += b3[1]; a2 += b3[2];
    a0 = a0 > 0.f ? a0 : 0.2f*a0;
    a1 = a1 > 0.f ? a1 : 0.2f*a1;
    a2 = a2 > 0.f ? a2 : 0.2f*a2;
    rgb[((size_t)(b*3 + 0) << 14) + pix] = a0;
    rgb[((size_t)(b*3 + 1) << 14) + pix] = a1;
    rgb[((size_t)(b*3 + 2) << 14) + pix] = a2;
}

// ---------------- launch ----------------
extern "C" void kernel_launch(void* const* d_in, const int* in_sizes, int n_in,
                              void* d_out, int out_size)
{
    const float* x   = (const float*)d_in[0];
    const float* w   = (const float*)d_in[1];
    const float* w1  = (const float*)d_in[2];
    const float* b1  = (const float*)d_in[3];
    const float* a1w = (const float*)d_in[4];
    const float* a1b = (const float*)d_in[5];
    const float* w2  = (const float*)d_in[6];
    const float* b2  = (const float*)d_in[7];
    const float* a2w = (const float*)d_in[8];
    const float* a2b = (const float*)d_in[9];
    const float* w3  = (const float*)d_in[10];
    const float* b3  = (const float*)d_in[11];
    const float* a3w = (const float*)d_in[12];
    const float* a3b = (const float*)d_in[13];

    float* out_h   = (float*)d_out;                       // [4,256,128,128]
    float* out_rgb = out_h + (size_t)NB*COUT*NPIX;        // [4,3,128,128]

    float *p_xumod, *p_h1s2, *p_w1p, *p_w2p, *p_s2, *p_d1, *p_d2;
    cudaGetSymbolAddress((void**)&p_xumod, g_xumod);
    cudaGetSymbolAddress((void**)&p_h1s2,  g_h1s2);
    cudaGetSymbolAddress((void**)&p_w1p,   g_w1p);
    cudaGetSymbolAddress((void**)&p_w2p,   g_w2p);
    cudaGetSymbolAddress((void**)&p_s2,    g_s2);
    cudaGetSymbolAddress((void**)&p_d1,    g_d1);
    cudaGetSymbolAddress((void**)&p_d2,    g_d2);

    // styles + weight prep (tiny)
    style_kernel<<<16, 256>>>(w, a1w, a1b, a2w, a2b, a3w, a3b);
    demod_kernel<<<COUT, 256>>>(w1, CIN1, 0);
    demod_kernel<<<COUT, 256>>>(w2, COUT, 1);
    w3m_kernel<<<12, 256>>>(w3);
    repack_kernel<<<(CIN1*COUT*9 + 255)/256, 256>>>(w1, p_w1p, CIN1, COUT);
    repack_kernel<<<(COUT*COUT*9 + 255)/256, 256>>>(w2, p_w2p, COUT, COUT);

    // upsample + modulate
    upsample_kernel<<<(NB*CIN1*NPIX)/256, 256>>>(x);

    // conv1: 512 -> 256, demod d1, +b1, lrelu, * s2  -> g_h1s2
    {
        dim3 grid(64, COUT/64, NB);
        conv3x3_kernel<CIN1, true><<<grid, 256>>>(p_xumod, p_w1p, b1, p_d1, p_s2, p_h1s2, COUT);
    }
    // conv2: 256 -> 256, demod d2, +b2, lrelu -> h output
    {
        dim3 grid(64, COUT/64, NB);
        conv3x3_kernel<COUT, false><<<grid, 256>>>(p_h1s2, p_w2p, b2, p_d2, nullptr, out_h, COUT);
    }
    // to_rgb
    rgb_kernel<<<(NB*NPIX)/256, 256>>>(out_h, b3, out_rgb);
}

// round 4
// speedup vs baseline: 1.6544x; 1.6544x over previous
#include <cuda_runtime.h>
#include <cstdint>

// ---------------- problem constants ----------------
#define NB    4
#define CIN1  512
#define COUT  256
#define HOUT  128          // spatial after upsample
#define NPIX  (HOUT*HOUT)  // 16384

// ---------------- scratch (device globals; no allocation allowed) ----------
__device__ float g_xumod[NB*CIN1*NPIX];      // upsampled & style-modulated input (134 MB)
__device__ float g_h1s2 [NB*COUT*NPIX];      // conv1 output, lrelu'd, pre-scaled by s2 (67 MB)
__device__ float g_w1p  [CIN1*(COUT/64)*576];
__device__ float g_w2p  [COUT*(COUT/64)*576];
__device__ float g_s1[NB*CIN1];
__device__ float g_s2[NB*COUT];
__device__ float g_s3[NB*COUT];
__device__ float g_d1[NB*COUT];
__device__ float g_d2[NB*COUT];
__device__ float g_w3m[NB*3*COUT];

// ---------------- style affine: s = w @ aW^T + aB ----------------
__global__ void style_kernel(const float* __restrict__ w,
                             const float* __restrict__ a1w, const float* __restrict__ a1b,
                             const float* __restrict__ a2w, const float* __restrict__ a2b,
                             const float* __restrict__ a3w, const float* __restrict__ a3b)
{
    int idx = blockIdx.x * blockDim.x + threadIdx.x;   // 0..4095
    const float* arow; const float* bias; float* out; int b, i;
    if (idx < 2048)      { b = idx >> 9;  i = idx & 511; arow = a1w + (size_t)i*512; bias = a1b; out = g_s1 + b*CIN1 + i; }
    else if (idx < 3072) { int t = idx - 2048; b = t >> 8; i = t & 255; arow = a2w + (size_t)i*512; bias = a2b; out = g_s2 + b*COUT + i; }
    else if (idx < 4096) { int t = idx - 3072; b = t >> 8; i = t & 255; arow = a3w + (size_t)i*512; bias = a3b; out = g_s3 + b*COUT + i; }
    else return;
    const float* wrow = w + (size_t)b*512;
    float acc = 0.f;
    #pragma unroll 8
    for (int k = 0; k < 512; ++k) acc = fmaf(wrow[k], arow[k], acc);
    *out = acc + bias[i];
}

// ---------------- demod factors: d[b,o] = rsqrt( sum_i s^2 * sum_k w^2 + eps )
__global__ void demod_kernel(const float* __restrict__ wgt, int CIN, int which)
{
    const float* s = which ? g_s2 : g_s1;
    float*       d = which ? g_d2 : g_d1;
    int o = blockIdx.x;               // 0..255
    int tid = threadIdx.x;            // 256 threads
    float pb[NB] = {0.f, 0.f, 0.f, 0.f};
    for (int i = tid; i < CIN; i += 256) {
        const float* wp = wgt + (size_t)(o*CIN + i)*9;
        float r = 0.f;
        #pragma unroll
        for (int t = 0; t < 9; ++t) { float v = wp[t]; r = fmaf(v, v, r); }
        #pragma unroll
        for (int b = 0; b < NB; ++b) { float sv = s[b*CIN + i]; pb[b] = fmaf(r, sv*sv, pb[b]); }
    }
    __shared__ float red[256];
    for (int b = 0; b < NB; ++b) {
        red[tid] = pb[b];
        __syncthreads();
        for (int st = 128; st > 0; st >>= 1) {
            if (tid < st) red[tid] += red[tid + st];
            __syncthreads();
        }
        if (tid == 0) d[b*COUT + o] = rsqrtf(red[0] + 1e-8f);
        __syncthreads();
    }
}

// ---------------- fold s3 into w3: w3m[b,c,o] = w3[c,o] * s3[b,o] ----------
__global__ void w3m_kernel(const float* __restrict__ w3)
{
    int idx = blockIdx.x * blockDim.x + threadIdx.x;
    if (idx >= NB*3*COUT) return;
    int o = idx & 255;
    int c = (idx >> 8) % 3;
    int b = idx / 768;
    g_w3m[idx] = w3[c*COUT + o] * g_s3[b*COUT + o];
}

// ---------------- weight repack: [o][ci][9] -> [ci][ocb][oi*9+tap] ---------
__global__ void repack_kernel(const float* __restrict__ w, float* __restrict__ wp,
                              int CIN, int OC)
{
    int idx = blockIdx.x * blockDim.x + threadIdx.x;
    if (idx >= OC*CIN*9) return;
    int tap = idx % 9;
    int t   = idx / 9;
    int ci  = t % CIN;
    int o   = t / CIN;
    int ocb = o >> 6, oi = o & 63;
    wp[(size_t)(ci*(OC >> 6) + ocb)*576 + oi*9 + tap] = w[idx];
}

// ---------------- bilinear x2 upsample (half-pixel) + s1 modulation --------
__global__ void upsample_kernel(const float* __restrict__ x)
{
    int idx = blockIdx.x * blockDim.x + threadIdx.x;    // 2^25 total
    int X  = idx & 127;
    int Y  = (idx >> 7) & 127;
    int ci = (idx >> 14) & 511;
    int b  = idx >> 23;
    int jy = Y >> 1, jx = X >> 1;
    int ya = jy + ((Y & 1) ? 0 : -1);
    float wya = (Y & 1) ? 0.75f : 0.25f;
    int yb = ya + 1; float wyb = 1.f - wya;
    int xa = jx + ((X & 1) ? 0 : -1);
    float wxa = (X & 1) ? 0.75f : 0.25f;
    int xb = xa + 1; float wxb = 1.f - wxa;
    ya = max(ya, 0); yb = min(yb, 63);
    xa = max(xa, 0); xb = min(xb, 63);
    const float* src = x + ((size_t)(b*CIN1 + ci) << 12);   // 64*64
    float v = wya * (wxa*src[ya*64 + xa] + wxb*src[ya*64 + xb])
            + wyb * (wxa*src[yb*64 + xa] + wxb*src[yb*64 + xb]);
    g_xumod[idx] = v * g_s1[b*CIN1 + ci];
}

// ---------------- main 3x3 conv (shared weights, per-(b,o) demod epilogue) -
// block: (tile 16x16 px, 64 oc, batch). 256 thr, 8oc x 8px micro-tile/thread.
template<int CIN, bool POST>
__global__ __launch_bounds__(256, 2)
void conv3x3_kernel(const float* __restrict__ in,    // [B,CIN,128,128]
                    const float* __restrict__ wp,    // repacked [ci][ocb][576]
                    const float* __restrict__ bias,  // [OC]
                    const float* __restrict__ demod, // [B,OC]
                    const float* __restrict__ post,  // [B,OC] or unused
                    float* __restrict__ out,         // [B,OC,128,128]
                    int OC)
{
    __shared__ __align__(16) float sIn[2][18*19];
    __shared__ __align__(16) float sW [2][576];

    const int tid    = threadIdx.x;
    const int tileId = blockIdx.x;            // 0..63
    const int ocb    = blockIdx.y;
    const int b      = blockIdx.z;
    const int baseY  = (tileId >> 3) << 4;
    const int baseX  = (tileId & 7) << 4;
    const int ocBase = ocb << 6;
    const int nOcb   = OC >> 6;

    const int lane = tid & 31;
    const int warp = tid >> 5;                // oc group (8 ocs)
    const int row  = lane >> 1;               // 0..15
    const int x0   = (lane & 1) << 3;         // 0 or 8

    float acc[8][8];
    #pragma unroll
    for (int i = 0; i < 8; ++i)
        #pragma unroll
        for (int j = 0; j < 8; ++j) acc[i][j] = 0.f;

    auto loadStage = [&](int ci, int p) {
        const float* inBase = in + ((size_t)(b*CIN + ci) << 14);
        #pragma unroll
        for (int t = tid; t < 324; t += 256) {
            int r = t / 18, c = t % 18;
            int gy = baseY + r - 1, gx = baseX + c - 1;
            uint32_t sa = (uint32_t)__cvta_generic_to_shared(&sIn[p][r*19 + c]);
            if ((unsigned)gy < 128u && (unsigned)gx < 128u) {
                asm volatile("cp.async.ca.shared.global [%0], [%1], 4;\n"
                             :: "r"(sa), "l"(inBase + (gy << 7) + gx));
            } else {
                sIn[p][r*19 + c] = 0.f;
            }
        }
        if (tid < 144) {
            const float* g = wp + (size_t)(ci*nOcb + ocb)*576 + tid*4;
            uint32_t sa = (uint32_t)__cvta_generic_to_shared(&sW[p][tid*4]);
            asm volatile("cp.async.cg.shared.global [%0], [%1], 16;\n"
                         :: "r"(sa), "l"(g));
        }
        asm volatile("cp.async.commit_group;\n");
    };

    loadStage(0, 0);

    for (int ci = 0; ci < CIN; ++ci) {
        int p = ci & 1;
        asm volatile("cp.async.wait_group 0;\n" ::: "memory");
        __syncthreads();
        if (ci + 1 < CIN) loadStage(ci + 1, p ^ 1);

        #pragma unroll
        for (int kh = 0; kh < 3; ++kh) {
            #pragma unroll
            for (int kw = 0; kw < 3; ++kw) {
                float wv[8];
                #pragma unroll
                for (int i = 0; i < 8; ++i)
                    wv[i] = sW[p][(warp*8 + i)*9 + kh*3 + kw];
                #pragma unroll
                for (int j = 0; j < 8; ++j) {
                    float xv = sIn[p][(row + kh)*19 + x0 + kw + j];
                    #pragma unroll
                    for (int i = 0; i < 8; ++i)
                        acc[i][j] = fmaf(wv[i], xv, acc[i][j]);
                }
            }
        }
    }

    // epilogue: demod, bias, leaky-relu, optional post-scale (s2 for conv1)
    #pragma unroll
    for (int i = 0; i < 8; ++i) {
        int o = ocBase + warp*8 + i;
        float d  = demod[b*OC + o];
        float bs = bias[o];
        float ps = POST ? post[b*OC + o] : 1.f;
        float* op = out + ((size_t)(b*OC + o) << 14) + ((baseY + row) << 7) + baseX + x0;
        float v[8];
        #pragma unroll
        for (int j = 0; j < 8; ++j) {
            float t = fmaf(acc[i][j], d, bs);
            t = t > 0.f ? t : 0.2f*t;
            v[j] = POST ? t*ps : t;
        }
        *(float4*)(op)     = make_float4(v[0], v[1], v[2], v[3]);
        *(float4*)(op + 4) = make_float4(v[4], v[5], v[6], v[7]);
    }
}

// ---------------- to_rgb: 1x1 conv over 256 ch, no demod, + bias, lrelu ----
__global__ void rgb_kernel(const float* __restrict__ h,   // [B,256,128,128]
                           const float* __restrict__ b3,
                           float* __restrict__ rgb)       // [B,3,128,128]
{
    int idx = blockIdx.x * blockDim.x + threadIdx.x;      // 0..65535
    int pix = idx & (NPIX - 1);
    int b   = idx >> 14;
    const float* hp = h + ((size_t)b * COUT << 14) + pix;
    const float* wm = g_w3m + b*3*COUT;
    float a0 = 0.f, a1 = 0.f, a2 = 0.f;
    #pragma unroll 4
    for (int o = 0; o < COUT; ++o) {
        float hv = hp[(size_t)o << 14];
        a0 = fmaf(hv, wm[o],            a0);
        a1 = fmaf(hv, wm[COUT + o],     a1);
        a2 = fmaf(hv, wm[2*COUT + o],   a2);
    }
    a0 += b3[0]; a1 += b3[1]; a2 += b3[2];
    a0 = a0 > 0.f ? a0 : 0.2f*a0;
    a1 = a1 > 0.f ? a1 : 0.2f*a1;
    a2 = a2 > 0.f ? a2 : 0.2f*a2;
    rgb[((size_t)(b*3 + 0) << 14) + pix] = a0;
    rgb[((size_t)(b*3 + 1) << 14) + pix] = a1;
    rgb[((size_t)(b*3 + 2) << 14) + pix] = a2;
}

// ---------------- launch ----------------
extern "C" void kernel_launch(void* const* d_in, const int* in_sizes, int n_in,
                              void* d_out, int out_size)
{
    const float* x   = (const float*)d_in[0];
    const float* w   = (const float*)d_in[1];
    const float* w1  = (const float*)d_in[2];
    const float* b1  = (const float*)d_in[3];
    const float* a1w = (const float*)d_in[4];
    const float* a1b = (const float*)d_in[5];
    const float* w2  = (const float*)d_in[6];
    const float* b2  = (const float*)d_in[7];
    const float* a2w = (const float*)d_in[8];
    const float* a2b = (const float*)d_in[9];
    const float* w3  = (const float*)d_in[10];
    const float* b3  = (const float*)d_in[11];
    const float* a3w = (const float*)d_in[12];
    const float* a3b = (const float*)d_in[13];

    float* out_h   = (float*)d_out;                       // [4,256,128,128]
    float* out_rgb = out_h + (size_t)NB*COUT*NPIX;        // [4,3,128,128]

    float *p_xumod, *p_h1s2, *p_w1p, *p_w2p, *p_s2, *p_d1, *p_d2;
    cudaGetSymbolAddress((void**)&p_xumod, g_xumod);
    cudaGetSymbolAddress((void**)&p_h1s2,  g_h1s2);
    cudaGetSymbolAddress((void**)&p_w1p,   g_w1p);
    cudaGetSymbolAddress((void**)&p_w2p,   g_w2p);
    cudaGetSymbolAddress((void**)&p_s2,    g_s2);
    cudaGetSymbolAddress((void**)&p_d1,    g_d1);
    cudaGetSymbolAddress((void**)&p_d2,    g_d2);

    // styles + weight prep (tiny)
    style_kernel<<<16, 256>>>(w, a1w, a1b, a2w, a2b, a3w, a3b);
    demod_kernel<<<COUT, 256>>>(w1, CIN1, 0);
    demod_kernel<<<COUT, 256>>>(w2, COUT, 1);
    w3m_kernel<<<12, 256>>>(w3);
    repack_kernel<<<(CIN1*COUT*9 + 255)/256, 256>>>(w1, p_w1p, CIN1, COUT);
    repack_kernel<<<(COUT*COUT*9 + 255)/256, 256>>>(w2, p_w2p, COUT, COUT);

    // upsample + modulate
    upsample_kernel<<<(NB*CIN1*NPIX)/256, 256>>>(x);

    // conv1: 512 -> 256, demod d1, +b1, lrelu, * s2  -> g_h1s2
    {
        dim3 grid(64, COUT/64, NB);
        conv3x3_kernel<CIN1, true><<<grid, 256>>>(p_xumod, p_w1p, b1, p_d1, p_s2, p_h1s2, COUT);
    }
    // conv2: 256 -> 256, demod d2, +b2, lrelu -> h output
    {
        dim3 grid(64, COUT/64, NB);
        conv3x3_kernel<COUT, false><<<grid, 256>>>(p_h1s2, p_w2p, b2, p_d2, nullptr, out_h, COUT);
    }
    // to_rgb
    rgb_kernel<<<(NB*NPIX)/256, 256>>>(out_h, b3, out_rgb);
}

// round 7
// speedup vs baseline: 5.1088x; 3.0880x over previous
#include <cuda_runtime.h>
#include <cstdint>
#include <cstddef>

#define NB    4
#define CIN1  512
#define COUT  256
#define NPIX  (128*128)

__device__ float g_xpad [NB*130*130*CIN1];
__device__ float g_h1pad[NB*130*130*COUT];
__device__ float g_w1p  [9*COUT*CIN1];     // fragment-ordered
__device__ float g_w2p  [9*COUT*COUT];
__device__ float g_s1[NB*CIN1];
__device__ float g_s2[NB*COUT];
__device__ float g_s3[NB*COUT];
__device__ float g_d1[NB*COUT];
__device__ float g_d2[NB*COUT];
__device__ float g_w3m[NB*3*COUT];

__device__ __forceinline__ uint32_t smem_u32(const void* p) {
    uint32_t a;
    asm("{ .reg .u64 t; cvta.to.shared.u64 t, %1; cvt.u32.u64 %0, t; }" : "=r"(a) : "l"(p));
    return a;
}
__device__ __forceinline__ float tf32r(float v) {
    uint32_t r; asm("cvt.rna.tf32.f32 %0, %1;" : "=r"(r) : "f"(v));
    return __uint_as_float(r);
}
__device__ __forceinline__ void cpa16(uint32_t s, const void* g) {
    asm volatile("cp.async.cg.shared.global [%0], [%1], 16;\n" :: "r"(s), "l"(g));
}
__device__ __forceinline__ void mma_tf32(float* c, const uint32_t* a, const uint32_t* b) {
    asm volatile(
        "mma.sync.aligned.m16n8k8.row.col.f32.tf32.tf32.f32 "
        "{%0,%1,%2,%3}, {%4,%5,%6,%7}, {%8,%9}, {%0,%1,%2,%3};"
        : "+f"(c[0]), "+f"(c[1]), "+f"(c[2]), "+f"(c[3])
        : "r"(a[0]), "r"(a[1]), "r"(a[2]), "r"(a[3]), "r"(b[0]), "r"(b[1]));
}

// ---------------- prep kernels ----------------
__global__ void style_kernel(const float* __restrict__ w,
                             const float* __restrict__ a1w, const float* __restrict__ a1b,
                             const float* __restrict__ a2w, const float* __restrict__ a2b,
                             const float* __restrict__ a3w, const float* __restrict__ a3b)
{
    int idx = blockIdx.x * blockDim.x + threadIdx.x;
    const float* arow; const float* bias; float* out; int b, i;
    if (idx < 2048)      { b = idx >> 9;  i = idx & 511; arow = a1w + (size_t)i*512; bias = a1b; out = g_s1 + b*CIN1 + i; }
    else if (idx < 3072) { int t = idx - 2048; b = t >> 8; i = t & 255; arow = a2w + (size_t)i*512; bias = a2b; out = g_s2 + b*COUT + i; }
    else if (idx < 4096) { int t = idx - 3072; b = t >> 8; i = t & 255; arow = a3w + (size_t)i*512; bias = a3b; out = g_s3 + b*COUT + i; }
    else return;
    const float* wrow = w + (size_t)b*512;
    float acc = 0.f;
    #pragma unroll 8
    for (int k = 0; k < 512; ++k) acc = fmaf(wrow[k], arow[k], acc);
    *out = acc + bias[i];
}

__global__ void demod_kernel(const float* __restrict__ wgt, int CIN, int which)
{
    const float* s = which ? g_s2 : g_s1;
    float*       d = which ? g_d2 : g_d1;
    int o = blockIdx.x, tid = threadIdx.x;
    float pb[NB] = {0.f, 0.f, 0.f, 0.f};
    for (int i = tid; i < CIN; i += 256) {
        const float* wp = wgt + (size_t)(o*CIN + i)*9;
        float r = 0.f;
        #pragma unroll
        for (int t = 0; t < 9; ++t) { float v = wp[t]; r = fmaf(v, v, r); }
        #pragma unroll
        for (int b = 0; b < NB; ++b) { float sv = s[b*CIN + i]; pb[b] = fmaf(r, sv*sv, pb[b]); }
    }
    __shared__ float red[256];
    for (int b = 0; b < NB; ++b) {
        red[tid] = pb[b];
        __syncthreads();
        for (int st = 128; st > 0; st >>= 1) {
            if (tid < st) red[tid] += red[tid + st];
            __syncthreads();
        }
        if (tid == 0) d[b*COUT + o] = rsqrtf(red[0] + 1e-8f);
        __syncthreads();
    }
}

__global__ void w3m_kernel(const float* __restrict__ w3)
{
    int idx = blockIdx.x * blockDim.x + threadIdx.x;
    if (idx >= NB*3*COUT) return;
    int o = idx & 255, c = (idx >> 8) % 3, b = idx / 768;
    g_w3m[idx] = w3[c*COUT + o] * g_s3[b*COUT + o];
}

// repack w [cout][cin][tap] -> fragment-ordered blocks of 4096 floats:
// block = (tap*KB + kb)*2 + cb ; within: ((s*8+f)*32 + lane)*4 + r
// m = cb*128 + f*16 + (lane>>2) + 8*(r&1) ; ci = kb*32 + s*8 + (lane&3) + 4*(r>>1)
__global__ void repack_kernel(const float* __restrict__ w, float* __restrict__ wp, int CIN)
{
    int idx = blockIdx.x * blockDim.x + threadIdx.x;
    if (idx >= COUT*CIN*9) return;
    int KB = CIN >> 5;
    int r = idx & 3;
    int l = (idx >> 2) & 31;
    int f = (idx >> 7) & 7;
    int s = (idx >> 10) & 3;
    int rem = idx >> 12;
    int cb = rem & 1; rem >>= 1;
    int kb = rem % KB;
    int t  = rem / KB;
    int m  = cb*128 + f*16 + (l >> 2) + 8*(r & 1);
    int ci = kb*32 + s*8 + (l & 3) + 4*(r >> 1);
    wp[idx] = tf32r(w[((size_t)m*CIN + ci)*9 + t]);
}

template<int C>
__global__ void border_kernel(float* buf)
{
    int idx = blockIdx.x * blockDim.x + threadIdx.x;
    const int per = 516 * (C/4);
    if (idx >= NB*per) return;
    int b = idx / per, r = idx % per;
    int p = r / (C/4), v = r % (C/4);
    int py, px;
    if (p < 130)      { py = 0;           px = p; }
    else if (p < 260) { py = 129;         px = p - 130; }
    else if (p < 388) { py = p - 260 + 1; px = 0; }
    else              { py = p - 388 + 1; px = 129; }
    ((float4*)buf)[((size_t)(b*130 + py)*130 + px)*(C/4) + v] = make_float4(0.f,0.f,0.f,0.f);
}

// bilinear x2 upsample + s1 modulation -> NHWC padded (tf32-rounded)
__global__ void up_pad_kernel(const float* __restrict__ x)
{
    __shared__ float sm[32][33];
    int tx = threadIdx.x, ty = threadIdx.y;   // (32,8)
    int pix0 = blockIdx.x * 32;
    int c0   = blockIdx.y * 32;
    int b    = blockIdx.z;
    int Y = pix0 >> 7;
    int X = (pix0 & 127) + tx;
    int jy = Y >> 1, jx = X >> 1;
    int ya = jy + ((Y & 1) ? 0 : -1);
    float wya = (Y & 1) ? 0.75f : 0.25f;
    int yb = ya + 1; float wyb = 1.f - wya;
    int xa = jx + ((X & 1) ? 0 : -1);
    float wxa = (X & 1) ? 0.75f : 0.25f;
    int xb = xa + 1; float wxb = 1.f - wxa;
    ya = max(ya, 0); yb = min(yb, 63);
    xa = max(xa, 0); xb = min(xb, 63);
    #pragma unroll
    for (int i = 0; i < 4; ++i) {
        int c = c0 + i*8 + ty;
        const float* src = x + ((size_t)(b*CIN1 + c) << 12);
        float v = wya*(wxa*src[ya*64 + xa] + wxb*src[ya*64 + xb])
                + wyb*(wxa*src[yb*64 + xa] + wxb*src[yb*64 + xb]);
        sm[i*8 + ty][tx] = tf32r(v * g_s1[b*CIN1 + c]);
    }
    __syncthreads();
    #pragma unroll
    for (int i = 0; i < 4; ++i) {
        int prow = i*8 + ty;
        int xx = (pix0 + prow) & 127;
        g_xpad[((size_t)((b*130 + Y + 1)*130) + xx + 1)*CIN1 + c0 + tx] = sm[tx][prow];
    }
}

// ---------------- tf32 mma.sync implicit-GEMM 3x3 conv --------------------
// CTA: M=128 couts x N=256 pixels (2 rows). 8 warps of 64x64.
// grid = (64 row-pairs, 2 cout-blocks, NB)
#define STAGE_B  53248            // A 16384 + B 256*36*4
#define NSTG     3

template<int CIN, bool POST>
__global__ __launch_bounds__(256, 1)
void conv_mma(const float* __restrict__ in,     // NHWC pad [B,130,130,CIN] tf32
              const float* __restrict__ wp,     // fragment-ordered
              const float* __restrict__ bias,
              const float* __restrict__ demod,
              const float* __restrict__ post,
              float* __restrict__ outp)
{
    constexpr int KB   = CIN / 32;
    constexpr int ITER = 9 * KB;
    extern __shared__ __align__(16) char dsm[];
    const uint32_t base = smem_u32(dsm);

    const int tid  = threadIdx.x;
    const int wid  = tid >> 5;
    const int lane = tid & 31;
    const int g    = lane >> 2;          // group id
    const int t4   = lane & 3;           // thread-in-group
    const int wm   = wid >> 2;           // 0..1  (M warp)
    const int wn   = wid & 3;            // 0..3  (N warp)
    const int y0   = blockIdx.x * 2;
    const int cb   = blockIdx.y;
    const int b    = blockIdx.z;

    float acc[4][8][4];
    #pragma unroll
    for (int f = 0; f < 4; ++f)
        #pragma unroll
        for (int nf = 0; nf < 8; ++nf)
            #pragma unroll
            for (int r = 0; r < 4; ++r) acc[f][nf][r] = 0.f;

    auto load = [&](int it, int slot) {
        const int tp = it / KB, kb = it - tp*KB;
        const int dy = tp / 3, dx = tp - dy*3;
        const uint32_t sA = base + slot*STAGE_B;
        const uint32_t sB = sA + 16384;
        const float* Ab = wp + ((size_t)((tp*KB + kb)*2 + cb))*4096;
        #pragma unroll
        for (int i = 0; i < 4; ++i) {                        // A: 4096 floats
            int c = tid + i*256;
            cpa16(sA + c*16, Ab + c*4);
        }
        const float* Bb = in + ((size_t)((b*130 + y0 + dy)*130) + dx)*CIN + kb*32;
        #pragma unroll
        for (int i = 0; i < 8; ++i) {                        // B: 256 rows x 32 fl
            int c = tid + i*256;
            int row = c >> 3, col = c & 7;
            const float* src = Bb + ((size_t)((row >> 7)*130 + (row & 127)))*CIN + col*4;
            cpa16(sB + row*144 + col*16, src);
        }
        asm volatile("cp.async.commit_group;\n" ::: "memory");
    };

    load(0, 0); load(1, 1); load(2, 2);

    for (int it = 0; it < ITER; ++it) {
        const int slot = it % NSTG;
        asm volatile("cp.async.wait_group %0;\n" :: "n"(NSTG - 1) : "memory");
        __syncthreads();
        const uint32_t sA = base + slot*STAGE_B;
        const uint32_t sB = sA + 16384;
        #pragma unroll
        for (int s = 0; s < 4; ++s) {
            uint32_t a[4][4];
            #pragma unroll
            for (int f = 0; f < 4; ++f) {
                uint32_t ad = sA + ((s*8 + wm*4 + f)*32 + lane)*16;
                asm volatile("ld.shared.v4.b32 {%0,%1,%2,%3}, [%4];"
                             : "=r"(a[f][0]), "=r"(a[f][1]), "=r"(a[f][2]), "=r"(a[f][3])
                             : "r"(ad));
            }
            uint32_t bb[8][2];
            #pragma unroll
            for (int nf = 0; nf < 8; ++nf) {
                uint32_t ad = sB + ((wn*64 + nf*8 + g)*36 + s*8 + t4)*4;
                asm volatile("ld.shared.b32 %0, [%1];"      : "=r"(bb[nf][0]) : "r"(ad));
                asm volatile("ld.shared.b32 %0, [%1 + 16];" : "=r"(bb[nf][1]) : "r"(ad));
            }
            #pragma unroll
            for (int f = 0; f < 4; ++f)
                #pragma unroll
                for (int nf = 0; nf < 8; ++nf)
                    mma_tf32(acc[f][nf], a[f], bb[nf]);
        }
        __syncthreads();
        if (it + NSTG < ITER) load(it + NSTG, slot);
    }

    // ---------------- epilogue ----------------
    const int bo = b*256;
    #pragma unroll
    for (int f = 0; f < 4; ++f) {
        const int m0 = wm*64 + f*16 + g;
        const int m1 = m0 + 8;
        const int mg0 = cb*128 + m0, mg1 = cb*128 + m1;
        const float d0 = demod[bo + mg0], d1 = demod[bo + mg1];
        const float v0 = bias[mg0],       v1 = bias[mg1];
        const float p0 = POST ? post[bo + mg0] : 0.f;
        const float p1 = POST ? post[bo + mg1] : 0.f;
        #pragma unroll
        for (int nf = 0; nf < 8; ++nf) {
            const int n  = wn*64 + nf*8 + 2*t4;
            const int py = y0 + (n >> 7), px = n & 127;
            float c0 = fmaf(acc[f][nf][0], d0, v0); c0 = c0 > 0.f ? c0 : 0.2f*c0;
            float c1 = fmaf(acc[f][nf][1], d0, v0); c1 = c1 > 0.f ? c1 : 0.2f*c1;
            float c2 = fmaf(acc[f][nf][2], d1, v1); c2 = c2 > 0.f ? c2 : 0.2f*c2;
            float c3 = fmaf(acc[f][nf][3], d1, v1); c3 = c3 > 0.f ? c3 : 0.2f*c3;
            if (POST) {
                float* rp = outp + ((size_t)((b*130 + py + 1)*130) + 1 + px)*256;
                rp[mg0]       = tf32r(c0 * p0);
                rp[256 + mg0] = tf32r(c1 * p0);
                rp[mg1]       = tf32r(c2 * p1);
                rp[256 + mg1] = tf32r(c3 * p1);
            } else {
                float* o0 = outp + (((size_t)bo + mg0) << 14) + (py << 7) + px;
                float* o1 = outp + (((size_t)bo + mg1) << 14) + (py << 7) + px;
                *(float2*)o0 = make_float2(c0, c1);
                *(float2*)o1 = make_float2(c2, c3);
            }
        }
    }
}

// ---------------- to_rgb: 1x1 conv over 256 ch ----------------
__global__ void rgb_kernel(const float* __restrict__ h,
                           const float* __restrict__ b3,
                           float* __restrict__ rgb)
{
    int idx = blockIdx.x * blockDim.x + threadIdx.x;
    int pix = idx & (NPIX - 1);
    int b   = idx >> 14;
    const float* hp = h + ((size_t)b * COUT << 14) + pix;
    const float* wm = g_w3m + b*3*COUT;
    float a0 = 0.f, a1 = 0.f, a2 = 0.f;
    #pragma unroll 4
    for (int o = 0; o < COUT; ++o) {
        float hv = hp[(size_t)o << 14];
        a0 = fmaf(hv, wm[o],          a0);
        a1 = fmaf(hv, wm[COUT + o],   a1);
        a2 = fmaf(hv, wm[2*COUT + o], a2);
    }
    a0 += b3[0]; a1 += b3[1]; a2 += b3[2];
    a0 = a0 > 0.f ? a0 : 0.2f*a0;
    a1 = a1 > 0.f ? a1 : 0.2f*a1;
    a2 = a2 > 0.f ? a2 : 0.2f*a2;
    rgb[((size_t)(b*3 + 0) << 14) + pix] = a0;
    rgb[((size_t)(b*3 + 1) << 14) + pix] = a1;
    rgb[((size_t)(b*3 + 2) << 14) + pix] = a2;
}

// ---------------- launch ----------------
extern "C" void kernel_launch(void* const* d_in, const int* in_sizes, int n_in,
                              void* d_out, int out_size)
{
    const float* x   = (const float*)d_in[0];
    const float* w   = (const float*)d_in[1];
    const float* w1  = (const float*)d_in[2];
    const float* b1  = (const float*)d_in[3];
    const float* a1w = (const float*)d_in[4];
    const float* a1b = (const float*)d_in[5];
    const float* w2  = (const float*)d_in[6];
    const float* b2  = (const float*)d_in[7];
    const float* a2w = (const float*)d_in[8];
    const float* a2b = (const float*)d_in[9];
    const float* w3  = (const float*)d_in[10];
    const float* b3  = (const float*)d_in[11];
    const float* a3w = (const float*)d_in[12];
    const float* a3b = (const float*)d_in[13];

    float* out_h   = (float*)d_out;
    float* out_rgb = out_h + (size_t)NB*COUT*NPIX;

    float *p_xpad, *p_h1pad, *p_w1p, *p_w2p, *p_s2, *p_d1, *p_d2;
    cudaGetSymbolAddress((void**)&p_xpad,  g_xpad);
    cudaGetSymbolAddress((void**)&p_h1pad, g_h1pad);
    cudaGetSymbolAddress((void**)&p_w1p,   g_w1p);
    cudaGetSymbolAddress((void**)&p_w2p,   g_w2p);
    cudaGetSymbolAddress((void**)&p_s2,    g_s2);
    cudaGetSymbolAddress((void**)&p_d1,    g_d1);
    cudaGetSymbolAddress((void**)&p_d2,    g_d2);

    const int SMEM = NSTG * STAGE_B;   // 159744
    cudaFuncSetAttribute(conv_mma<CIN1, true>,  cudaFuncAttributeMaxDynamicSharedMemorySize, SMEM);
    cudaFuncSetAttribute(conv_mma<COUT, false>, cudaFuncAttributeMaxDynamicSharedMemorySize, SMEM);

    style_kernel<<<16, 256>>>(w, a1w, a1b, a2w, a2b, a3w, a3b);
    demod_kernel<<<COUT, 256>>>(w1, CIN1, 0);
    demod_kernel<<<COUT, 256>>>(w2, COUT, 1);
    w3m_kernel<<<12, 256>>>(w3);
    repack_kernel<<<(COUT*CIN1*9 + 255)/256, 256>>>(w1, p_w1p, CIN1);
    repack_kernel<<<(COUT*COUT*9 + 255)/256, 256>>>(w2, p_w2p, COUT);
    border_kernel<CIN1><<<(NB*516*(CIN1/4) + 255)/256, 256>>>(p_xpad);
    border_kernel<COUT><<<(NB*516*(COUT/4) + 255)/256, 256>>>(p_h1pad);

    {
        dim3 grid(NPIX/32, CIN1/32, NB);
        up_pad_kernel<<<grid, dim3(32, 8)>>>(x);
    }
    {
        dim3 grid(64, 2, NB);
        conv_mma<CIN1, true ><<<grid, 256, SMEM>>>(p_xpad,  p_w1p, b1, p_d1, p_s2, p_h1pad);
        conv_mma<COUT, false><<<grid, 256, SMEM>>>(p_h1pad, p_w2p, b2, p_d2, nullptr, out_h);
    }
    rgb_kernel<<<(NB*NPIX)/256, 256>>>(out_h, b3, out_rgb);
}